// round 13
// baseline (speedup 1.0000x reference)
#include <cuda_runtime.h>
#include <cuda_fp16.h>
#include <cstdint>

#define NNODES 32768
#define FF 256
#define AHS 264      // half-buffer row stride (halfs)
#define KFS 260      // f32-buffer row stride (floats)
#define NTHREADS 512

// Pre-transposed half weights, layout [k][n]: 0=Wq 1=Wk 2=Wv 3=lin_w^T
__device__ __half g_wt[4][65536];

__global__ void prep_w(const float* __restrict__ Wq, const float* __restrict__ Wk,
                       const float* __restrict__ Wv, const float* __restrict__ lw) {
    int idx = blockIdx.x * 256 + threadIdx.x;   // idx = k*256 + n
    int k = idx >> 8, n = idx & 255;
    g_wt[0][idx] = __float2half(Wq[idx]);
    g_wt[1][idx] = __float2half(Wk[idx]);
    g_wt[2][idx] = __float2half(Wv[idx]);
    g_wt[3][idx] = __float2half(lw[n * 256 + k]);   // transpose [out,in] -> [k][n]
}

__device__ __forceinline__ uint32_t smem_u32(const void* p) {
    uint32_t a;
    asm("{.reg .u64 t; cvta.to.shared.u64 t, %1; cvt.u32.u64 %0, t;}" : "=r"(a) : "l"(p));
    return a;
}
__device__ __forceinline__ void ldsm4(uint32_t a, uint32_t* r) {
    asm volatile("ldmatrix.sync.aligned.m8n8.x4.shared.b16 {%0,%1,%2,%3},[%4];"
                 : "=r"(r[0]), "=r"(r[1]), "=r"(r[2]), "=r"(r[3]) : "r"(a));
}
__device__ __forceinline__ void ldsm4t(uint32_t a, uint32_t* r) {
    asm volatile("ldmatrix.sync.aligned.m8n8.x4.trans.shared.b16 {%0,%1,%2,%3},[%4];"
                 : "=r"(r[0]), "=r"(r[1]), "=r"(r[2]), "=r"(r[3]) : "r"(a));
}
__device__ __forceinline__ void hmma(float* c, const uint32_t* a, const uint32_t* b) {
    asm volatile("mma.sync.aligned.m16n8k16.row.col.f32.f16.f16.f32 "
                 "{%0,%1,%2,%3},{%4,%5,%6,%7},{%8,%9},{%0,%1,%2,%3};"
                 : "+f"(c[0]), "+f"(c[1]), "+f"(c[2]), "+f"(c[3])
                 : "r"(a[0]), "r"(a[1]), "r"(a[2]), "r"(a[3]), "r"(b[0]), "r"(b[1]));
}
__device__ __forceinline__ void cpasync16(uint32_t dst, const void* src) {
    asm volatile("cp.async.ca.shared.global [%0],[%1],16;" :: "r"(dst), "l"(src) : "memory");
}

// 64x256 @ 256x256 GEMM core, 16 warps: warp tile 16m x 64n (4M x 4N).
// A half in smem (stride AHS), W half global [k][n], 32x256 chunks double-buffered.
__device__ __forceinline__ void gemm_core(uint32_t sAh, uint32_t sBs,
                                          const __half* __restrict__ Wg,
                                          float acc[8][4], int tid) {
    const int lane = tid & 31, warp = tid >> 5;
    const int m0w = (warp >> 2) * 16, n0w = (warp & 3) * 64;
#pragma unroll
    for (int nt = 0; nt < 8; nt++)
#pragma unroll
        for (int e = 0; e < 4; e++) acc[nt][e] = 0.f;

    const uint32_t aBase = sAh + (uint32_t)(((m0w + (lane & 15)) * AHS) + ((lane >> 4) * 8)) * 2;
    const uint32_t bLane = (uint32_t)(((lane & 15) * AHS) + n0w + ((lane >> 4) * 8)) * 2;

    // prefetch chunk 0 -> buf 0 (1024 x 16B per chunk)
#pragma unroll
    for (int i = 0; i < 2; i++) {
        int idx = tid + i * NTHREADS;
        int k = idx >> 5, nb = (idx & 31) * 8;
        cpasync16(sBs + (uint32_t)(k * AHS + nb) * 2, Wg + k * 256 + nb);
    }
    asm volatile("cp.async.commit_group;" ::: "memory");

    for (int c = 0; c < 8; c++) {
        const uint32_t bufOff = (uint32_t)(c & 1) * 32 * AHS * 2;
        if (c < 7) {
            const uint32_t nbuf = (uint32_t)((c + 1) & 1) * 32 * AHS * 2;
#pragma unroll
            for (int i = 0; i < 2; i++) {
                int idx = tid + i * NTHREADS;
                int k = idx >> 5, nb = (idx & 31) * 8;
                cpasync16(sBs + nbuf + (uint32_t)(k * AHS + nb) * 2,
                          Wg + (c + 1) * 32 * 256 + k * 256 + nb);
            }
            asm volatile("cp.async.commit_group;" ::: "memory");
            asm volatile("cp.async.wait_group 1;" ::: "memory");
        } else {
            asm volatile("cp.async.wait_group 0;" ::: "memory");
        }
        __syncthreads();
#pragma unroll
        for (int kk = 0; kk < 2; kk++) {
            uint32_t a[4], b[8][2];
            ldsm4(aBase + (uint32_t)(c * 32 + kk * 16) * 2, a);
#pragma unroll
            for (int nt4 = 0; nt4 < 4; nt4++) {
                uint32_t r[4];
                ldsm4t(sBs + bufOff + bLane + (uint32_t)(kk * 16 * AHS + nt4 * 16) * 2, r);
                b[nt4 * 2][0] = r[0]; b[nt4 * 2][1] = r[1];
                b[nt4 * 2 + 1][0] = r[2]; b[nt4 * 2 + 1][1] = r[3];
            }
#pragma unroll
            for (int nt = 0; nt < 8; nt++)
                hmma(acc[nt], a, b[nt]);
        }
        __syncthreads();
    }
}

__device__ __forceinline__ void store_half(__half* D, float acc[8][4], int tid) {
    const int lane = tid & 31, warp = tid >> 5;
    const int m0w = (warp >> 2) * 16, n0w = (warp & 3) * 64;
#pragma unroll
    for (int nt = 0; nt < 8; nt++) {
        int r = m0w + (lane >> 2);
        int c = n0w + nt * 8 + (lane & 3) * 2;
        *(__half2*)(D + r * AHS + c) = __floats2half2_rn(acc[nt][0], acc[nt][1]);
        *(__half2*)(D + (r + 8) * AHS + c) = __floats2half2_rn(acc[nt][2], acc[nt][3]);
    }
}

// smem layout (bytes):
#define SO_BIAS 0
#define SO_AH   1024
#define SO_QH   34816
#define SO_VH   68608
#define SO_KF   102400
#define SO_BS   168960
#define SMEM_TOTAL 202752

__global__ void __launch_bounds__(NTHREADS, 1)
fused_k(const float* __restrict__ inputs, const float* __restrict__ EC,
        const float* __restrict__ pos, const float* __restrict__ lin_b,
        float* __restrict__ out, float* __restrict__ ST) {
    extern __shared__ char sh[];
    float*  sBias = (float*)(sh + SO_BIAS);
    __half* Ah = (__half*)(sh + SO_AH);   // EC -> temporal (persists to epilogue)
    __half* Qh = (__half*)(sh + SO_QH);   // q (half)
    __half* Vh = (__half*)(sh + SO_VH);   // v -> ctx-half
    float*  Kf = (float*)(sh + SO_KF);    // k fp32 -> ctx fp32
    __half* Bs = (__half*)(sh + SO_BS);   // weight double buffer

    const int tid = threadIdx.x;
    const int cta = blockIdx.x;
    const size_t rowG0 = (size_t)cta * 64;

    const uint32_t sAh = smem_u32(Ah), sBs = smem_u32(Bs);
    if (tid < 256) sBias[tid] = lin_b[tid];

    // ---- stage EC -> Ah (4096 float4) ----
#pragma unroll
    for (int i = 0; i < 8; i++) {
        int idx = tid + i * NTHREADS;
        int r = idx >> 6, c = (idx & 63) * 4;
        float4 t = *(const float4*)(EC + (rowG0 + r) * FF + c);
        __half2* d = (__half2*)(Ah + r * AHS + c);
        d[0] = __floats2half2_rn(t.x, t.y);
        d[1] = __floats2half2_rn(t.z, t.w);
    }
    float acc[8][4];

    // ---- K = EC @ Wk -> Kf (fp32) ----
    gemm_core(sAh, sBs, g_wt[1], acc, tid);
    {
        const int lane = tid & 31, warp = tid >> 5;
        const int m0w = (warp >> 2) * 16, n0w = (warp & 3) * 64;
#pragma unroll
        for (int nt = 0; nt < 8; nt++) {
            int r = m0w + (lane >> 2);
            int c = n0w + nt * 8 + (lane & 3) * 2;
            *(float2*)(Kf + r * KFS + c) = make_float2(acc[nt][0], acc[nt][1]);
            *(float2*)(Kf + (r + 8) * KFS + c) = make_float2(acc[nt][2], acc[nt][3]);
        }
    }
    __syncthreads();

    // ---- stage temporal = inputs + pos -> Ah ----
#pragma unroll
    for (int i = 0; i < 8; i++) {
        int idx = tid + i * NTHREADS;
        int r = idx >> 6, c = (idx & 63) * 4;
        float4 t = *(const float4*)(inputs + (rowG0 + r) * FF + c);
        float4 p = *(const float4*)(pos + (r & 15) * FF + c);
        t.x += p.x; t.y += p.y; t.z += p.z; t.w += p.w;
        __half2* d = (__half2*)(Ah + r * AHS + c);
        d[0] = __floats2half2_rn(t.x, t.y);
        d[1] = __floats2half2_rn(t.z, t.w);
    }
    // ---- Q = temporal @ Wq -> Qh ----
    gemm_core(sAh, sBs, g_wt[0], acc, tid);
    store_half(Qh, acc, tid);
    // ---- V = temporal @ Wv -> Vh ----
    gemm_core(sAh, sBs, g_wt[2], acc, tid);
    store_half(Vh, acc, tid);
    __syncthreads();

    // ---- attention: thread owns 2 (i64, h) pairs; vectorized LDS ----
    const int i64 = tid & 63;
    const int node = i64 >> 4;
    const int hbase = tid >> 6;          // 0..7
    float pr[2][16];
#pragma unroll
    for (int p = 0; p < 2; p++) {
        const int h = (hbase + p * 8) & 15;
        float qf[16];
        {
            uint4 qa = *(const uint4*)(Qh + i64 * AHS + h * 16);
            uint4 qb = *(const uint4*)(Qh + i64 * AHS + h * 16 + 8);
            const __half2* pa = (const __half2*)&qa;
            const __half2* pb = (const __half2*)&qb;
#pragma unroll
            for (int e = 0; e < 4; e++) {
                float2 t0 = __half22float2(pa[e]);
                float2 t1 = __half22float2(pb[e]);
                qf[2 * e] = t0.x; qf[2 * e + 1] = t0.y;
                qf[8 + 2 * e] = t1.x; qf[9 + 2 * e] = t1.y;
            }
        }
        float sc[16], mx = -1e30f;
#pragma unroll
        for (int j = 0; j < 16; j++) {
            const float4* kr = (const float4*)(Kf + (node * 16 + j) * KFS + h * 16);
            float4 k0 = kr[0], k1 = kr[1], k2 = kr[2], k3 = kr[3];
            float s = qf[0]*k0.x + qf[1]*k0.y + qf[2]*k0.z + qf[3]*k0.w
                    + qf[4]*k1.x + qf[5]*k1.y + qf[6]*k1.z + qf[7]*k1.w
                    + qf[8]*k2.x + qf[9]*k2.y + qf[10]*k2.z + qf[11]*k2.w
                    + qf[12]*k3.x + qf[13]*k3.y + qf[14]*k3.z + qf[15]*k3.w;
            s *= 0.25f;
            sc[j] = s; mx = fmaxf(mx, s);
        }
        float sum = 0.f;
#pragma unroll
        for (int j = 0; j < 16; j++) { sc[j] = __expf(sc[j] - mx); sum += sc[j]; }
        const float inv = 1.f / sum;
#pragma unroll
        for (int j = 0; j < 16; j++) pr[p][j] = sc[j] * inv;
        float* stp = ST + (rowG0 + i64) * FF + h * 16;
#pragma unroll
        for (int j0 = 0; j0 < 16; j0 += 4)
            __stcs((float4*)(stp + j0),
                   make_float4(pr[p][j0], pr[p][j0 + 1], pr[p][j0 + 2], pr[p][j0 + 3]));
    }
    __syncthreads();   // all Kf reads (scores) done before ctx overwrites Kf

    // ---- ctx = P @ V -> Kf (fp32), vectorized Vh reads ----
#pragma unroll
    for (int p = 0; p < 2; p++) {
        const int h = (hbase + p * 8) & 15;
        float ct[16];
#pragma unroll
        for (int d = 0; d < 16; d++) ct[d] = 0.f;
#pragma unroll
        for (int j = 0; j < 16; j++) {
            const float pj = pr[p][j];
            uint4 va = *(const uint4*)(Vh + (node * 16 + j) * AHS + h * 16);
            uint4 vb = *(const uint4*)(Vh + (node * 16 + j) * AHS + h * 16 + 8);
            const __half2* pa = (const __half2*)&va;
            const __half2* pb = (const __half2*)&vb;
#pragma unroll
            for (int e = 0; e < 4; e++) {
                float2 t0 = __half22float2(pa[e]);
                float2 t1 = __half22float2(pb[e]);
                ct[2 * e]     += pj * t0.x;
                ct[2 * e + 1] += pj * t0.y;
                ct[8 + 2 * e] += pj * t1.x;
                ct[9 + 2 * e] += pj * t1.y;
            }
        }
        float* cd = Kf + i64 * KFS + h * 16;
#pragma unroll
        for (int d0 = 0; d0 < 16; d0 += 4)
            *(float4*)(cd + d0) = make_float4(ct[d0], ct[d0 + 1], ct[d0 + 2], ct[d0 + 3]);
    }
    __syncthreads();   // Vh reads done -> safe to overwrite with ctx-half

    // ---- ctx fp32 -> Vh half (ff A operand), 8192 half2 ----
#pragma unroll
    for (int i = 0; i < 16; i++) {
        int idx = tid + i * NTHREADS;
        int r = idx >> 7, c2 = (idx & 127) * 2;
        float2 t = *(const float2*)(Kf + r * KFS + c2);
        *(__half2*)(Vh + r * AHS + c2) = __floats2half2_rn(t.x, t.y);
    }
    __syncthreads();

    // ---- FF GEMM: relu(ctx @ lin_w^T + b) + ctx + temporal, mean over T ----
    gemm_core(smem_u32(Vh), sBs, g_wt[3], acc, tid);
    {
        const int lane = tid & 31, warp = tid >> 5;
        const int m0w = (warp >> 2) * 16, n0w = (warp & 3) * 64;
        const int nodeg = cta * 4 + (warp >> 2);   // 16 rows per m-warp = one node
#pragma unroll
        for (int nt = 0; nt < 8; nt++) {
            const int r1 = m0w + (lane >> 2);
            const int r2 = r1 + 8;
            const int c0 = n0w + nt * 8 + (lane & 3) * 2;
            const float b0 = sBias[c0], b1 = sBias[c0 + 1];
            float y00 = fmaxf(acc[nt][0] + b0, 0.f) + Kf[r1 * KFS + c0]     + __half2float(Ah[r1 * AHS + c0]);
            float y01 = fmaxf(acc[nt][1] + b1, 0.f) + Kf[r1 * KFS + c0 + 1] + __half2float(Ah[r1 * AHS + c0 + 1]);
            float y10 = fmaxf(acc[nt][2] + b0, 0.f) + Kf[r2 * KFS + c0]     + __half2float(Ah[r2 * AHS + c0]);
            float y11 = fmaxf(acc[nt][3] + b1, 0.f) + Kf[r2 * KFS + c0 + 1] + __half2float(Ah[r2 * AHS + c0 + 1]);
            float s0 = y00 + y10, s1 = y01 + y11;
#pragma unroll
            for (int off = 16; off >= 4; off >>= 1) {
                s0 += __shfl_xor_sync(0xffffffffu, s0, off);
                s1 += __shfl_xor_sync(0xffffffffu, s1, off);
            }
            if ((lane >> 2) == 0) {
                out[(size_t)nodeg * FF + c0]     = s0 * (1.f / 16.f);
                out[(size_t)nodeg * FF + c0 + 1] = s1 * (1.f / 16.f);
            }
        }
    }
}

extern "C" void kernel_launch(void* const* d_in, const int* in_sizes, int n_in,
                              void* d_out, int out_size) {
    (void)in_sizes; (void)n_in; (void)out_size;
    const float* inputs = (const float*)d_in[0];
    const float* EC     = (const float*)d_in[1];
    const float* pos    = (const float*)d_in[2];
    const float* Wq     = (const float*)d_in[3];
    const float* Wk     = (const float*)d_in[4];
    const float* Wv     = (const float*)d_in[5];
    const float* lin_w  = (const float*)d_in[6];
    const float* lin_b  = (const float*)d_in[7];

    float* out = (float*)d_out;                       // [N, F]
    float* ST  = out + (size_t)NNODES * FF;           // [N, T, H*T]

    cudaFuncSetAttribute(fused_k, cudaFuncAttributeMaxDynamicSharedMemorySize, SMEM_TOTAL);

    prep_w<<<256, 256>>>(Wq, Wk, Wv, lin_w);
    fused_k<<<NNODES / 4, NTHREADS, SMEM_TOTAL>>>(inputs, EC, pos, lin_b, out, ST);
}